// round 15
// baseline (speedup 1.0000x reference)
#include <cuda_runtime.h>
#include <cuda_fp16.h>
#include <cstdint>

// Problem constants
#define SEQ    4096
#define DMODEL 1024
#define D3     3072
#define NHEAD  16
#define HDIM   64
#define WIN    512
#define NCHUNK 8

// Scratch (device globals: allocation-free per harness rules)
__device__ __half g_qkvh[SEQ * D3];           // qkv hi plane (x256)
__device__ __half g_qkvl[SEQ * D3];           // qkv lo plane
__device__ __half g_xh[SEQ * DMODEL];
__device__ __half g_xl[SEQ * DMODEL];
__device__ __half g_wqh[D3 * DMODEL];         // w_qkv^T planes [N][K]
__device__ __half g_wql[D3 * DMODEL];
__device__ __half g_ath[SEQ * DMODEL];        // attn split planes (x256)
__device__ __half g_atl[SEQ * DMODEL];
__device__ __half g_woh[DMODEL * DMODEL];     // w_out^T planes [N][K]
__device__ __half g_wol[DMODEL * DMODEL];

// ---------------------------------------------------------------------------
// helpers
// ---------------------------------------------------------------------------
__device__ __forceinline__ void split_h(float x, __half& hi, __half& lo) {
    hi = __float2half_rn(x);
    lo = __float2half_rn(x - __half2float(hi));
}
__device__ __forceinline__ uint32_t split_pack(float x, float y, uint32_t& lo) {
    __half2 h2 = __float22half2_rn(make_float2(x, y));
    float2 hf = __half22float2(h2);
    __half2 l2 = __float22half2_rn(make_float2(x - hf.x, y - hf.y));
    lo = *reinterpret_cast<uint32_t*>(&l2);
    return *reinterpret_cast<uint32_t*>(&h2);
}
__device__ __forceinline__ float fexp2(float x) {
    float r;
    asm("ex2.approx.f32 %0, %1;" : "=f"(r) : "f"(x));
    return r;
}

#define MMA_F16(d, a0, a1, a2, a3, b0, b1)                                     \
    asm volatile(                                                              \
        "mma.sync.aligned.m16n8k16.row.col.f32.f16.f16.f32 "                   \
        "{%0,%1,%2,%3}, {%4,%5,%6,%7}, {%8,%9}, {%0,%1,%2,%3};"                \
        : "+f"((d)[0]), "+f"((d)[1]), "+f"((d)[2]), "+f"((d)[3])               \
        : "r"(a0), "r"(a1), "r"(a2), "r"(a3), "r"(b0), "r"(b1))

#define LDSM_X4(r0, r1, r2, r3, addr)                                          \
    asm volatile("ldmatrix.sync.aligned.m8n8.x4.shared.b16 {%0,%1,%2,%3}, [%4];" \
        : "=r"(r0), "=r"(r1), "=r"(r2), "=r"(r3) : "r"(addr))

#define LDSM_X4_T(r0, r1, r2, r3, addr)                                        \
    asm volatile("ldmatrix.sync.aligned.m8n8.x4.trans.shared.b16 {%0,%1,%2,%3}, [%4];" \
        : "=r"(r0), "=r"(r1), "=r"(r2), "=r"(r3) : "r"(addr))

#define CP_ASYNC16(dst, src)                                                   \
    asm volatile("cp.async.cg.shared.global [%0], [%1], 16;"                   \
        :: "r"(dst), "l"(src))
#define CP_COMMIT()  asm volatile("cp.async.commit_group;" ::: "memory")
#define CP_WAIT0()   asm volatile("cp.async.wait_group 0;" ::: "memory")
#define CP_WAIT1()   asm volatile("cp.async.wait_group 1;" ::: "memory")

// ---------------------------------------------------------------------------
// Split kernels
// ---------------------------------------------------------------------------
__global__ __launch_bounds__(256) void split2h(const float* __restrict__ in,
                                               __half* __restrict__ hp,
                                               __half* __restrict__ lp, int n) {
    const int idx = (blockIdx.x * 256 + threadIdx.x) * 4;
    if (idx >= n) return;
    const float4 v = *(const float4*)(in + idx);
    uint32_t l0, l1;
    const uint32_t h0 = split_pack(v.x * 256.f, v.y * 256.f, l0);
    const uint32_t h1 = split_pack(v.z * 256.f, v.w * 256.f, l1);
    *(uint2*)(hp + idx) = make_uint2(h0, h1);
    *(uint2*)(lp + idx) = make_uint2(l0, l1);
}

__global__ void split2h_t(const float* __restrict__ w,
                          __half* __restrict__ th, __half* __restrict__ tl,
                          int Kd, int Nd) {
    __shared__ float tile[32][33];
    const int k0 = blockIdx.y * 32, n0 = blockIdx.x * 32;
    const int tx = threadIdx.x, ty = threadIdx.y;
    for (int r = ty; r < 32; r += 8)
        tile[r][tx] = w[(size_t)(k0 + r) * Nd + n0 + tx];
    __syncthreads();
    for (int r = ty; r < 32; r += 8) {
        __half h, l;
        split_h(tile[tx][r] * 256.f, h, l);
        const size_t o = (size_t)(n0 + r) * Kd + k0 + tx;
        th[o] = h; tl[o] = l;
    }
}

// ---------------------------------------------------------------------------
// 3xFP16 GEMM (m16n8k16). R15: 4-stage BK=16 cp.async ring, 2 groups in
// flight (issue runs 2 compute blocks ahead). Stage s owns 16B-chunk pair
// {2s, 2s+1} of each 128B row; same swizzle; same 64 KB smem; 2 CTAs/SM.
// ---------------------------------------------------------------------------
template <bool SPLIT_OUT>
__global__ __launch_bounds__(256, 2) void gemm_f16x3(
    const __half* __restrict__ Ahg, const __half* __restrict__ Alg,
    const __half* __restrict__ Bhg, const __half* __restrict__ Blg,
    float* __restrict__ Cf, __half* __restrict__ Ch, __half* __restrict__ Cl,
    int M, int N, int K, float outscale) {
    extern __shared__ char smc[];

    const int tid  = threadIdx.x;
    const int lane = tid & 31;
    const int warp = tid >> 5;
    const int warp_m = warp >> 2;
    const int warp_n = warp & 3;

    const int m0 = blockIdx.y * 128;
    const int n0 = blockIdx.x * 128;

    const int lm_row  = (lane & 7) + ((lane >> 3) & 1) * 8;
    const int lm_csel = lane >> 4;
    const int gs  = lane >> 4;
    const int gc2 = (lane >> 3) & 1;

    float acc[4][4][4] = {};

    const uint32_t sb = (uint32_t)__cvta_generic_to_shared(smc);

    const __half* base0 = Ahg + (size_t)m0 * K;
    const __half* base1 = Alg + (size_t)m0 * K;
    const __half* base2 = Bhg + (size_t)n0 * K;
    const __half* base3 = Blg + (size_t)n0 * K;

    const int NIT = K >> 4;     // BK = 16

    // issue loads for k-iteration it into stage (it & 3)
    auto issue = [&](int it) {
        const int k0 = it << 4;
        const int cbase = (it & 3) << 1;
        #pragma unroll
        for (int i = 0; i < 4; i++) {
            const int lin = tid + i * 256;     // 0..1023
            const int pl  = lin >> 8;          // 0:Ah 1:Al 2:Bh 3:Bl
            const int rem = lin & 255;
            const int row = rem >> 1;          // 0..127
            const int ch2 = rem & 1;           // chunk within stage
            const __half* src =
                (pl == 0 ? base0 : pl == 1 ? base1 : pl == 2 ? base2 : base3)
                + (size_t)row * K + k0 + ch2 * 8;
            const uint32_t dst = sb + pl * 16384 + row * 128 +
                                 (((cbase + ch2) ^ (row & 7)) << 4);
            CP_ASYNC16(dst, src);
        }
        CP_COMMIT();
    };

    issue(0);
    issue(1);
    for (int it = 0; it < NIT; it++) {
        if (it + 1 < NIT) CP_WAIT1(); else CP_WAIT0();
        __syncthreads();
        if (it + 2 < NIT) issue(it + 2);

        const int c0 = (it & 3) << 1;
        uint32_t aH[4][4], aL[4][4];
        #pragma unroll
        for (int mf = 0; mf < 4; mf++) {
            const int m = warp_m * 64 + mf * 16 + lm_row;
            const uint32_t off =
                (uint32_t)(m * 128 + (((c0 + lm_csel) ^ (m & 7)) << 4));
            LDSM_X4(aH[mf][0], aH[mf][1], aH[mf][2], aH[mf][3], sb + off);
            LDSM_X4(aL[mf][0], aL[mf][1], aL[mf][2], aL[mf][3], sb + 16384 + off);
        }
        uint32_t bH[2][4], bL[2][4];
        #pragma unroll
        for (int p = 0; p < 2; p++) {
            const int n = warp_n * 32 + (2 * p + gs) * 8 + (lane & 7);
            const uint32_t off =
                (uint32_t)(n * 128 + (((c0 + gc2) ^ (n & 7)) << 4));
            LDSM_X4(bH[p][0], bH[p][1], bH[p][2], bH[p][3], sb + 32768 + off);
            LDSM_X4(bL[p][0], bL[p][1], bL[p][2], bL[p][3], sb + 49152 + off);
        }
        #pragma unroll
        for (int p = 0; p < 2; p++)
            #pragma unroll
            for (int sub = 0; sub < 2; sub++) {
                const int nf = 2 * p + sub;
                const uint32_t bh0 = bH[p][2 * sub], bh1 = bH[p][2 * sub + 1];
                const uint32_t bl0 = bL[p][2 * sub], bl1 = bL[p][2 * sub + 1];
                #pragma unroll
                for (int mf = 0; mf < 4; mf++) {
                    MMA_F16(acc[mf][nf], aH[mf][0], aH[mf][1], aH[mf][2], aH[mf][3], bh0, bh1);
                    MMA_F16(acc[mf][nf], aH[mf][0], aH[mf][1], aH[mf][2], aH[mf][3], bl0, bl1);
                    MMA_F16(acc[mf][nf], aL[mf][0], aL[mf][1], aL[mf][2], aL[mf][3], bh0, bh1);
                }
            }
        __syncthreads();
    }

    const int row_in = lane >> 2;
    const int col_in = 2 * (lane & 3);
    #pragma unroll
    for (int mf = 0; mf < 4; mf++) {
        const int gr = m0 + warp_m * 64 + mf * 16 + row_in;
        #pragma unroll
        for (int nf = 0; nf < 4; nf++) {
            const int gc = n0 + warp_n * 32 + nf * 8 + col_in;
            if (SPLIT_OUT) {
                uint32_t lo;
                uint32_t hi = split_pack(acc[mf][nf][0] * outscale,
                                         acc[mf][nf][1] * outscale, lo);
                *(uint32_t*)(Ch + (size_t)gr * N + gc) = hi;
                *(uint32_t*)(Cl + (size_t)gr * N + gc) = lo;
                hi = split_pack(acc[mf][nf][2] * outscale,
                                acc[mf][nf][3] * outscale, lo);
                *(uint32_t*)(Ch + (size_t)(gr + 8) * N + gc) = hi;
                *(uint32_t*)(Cl + (size_t)(gr + 8) * N + gc) = lo;
            } else {
                *(float2*)(Cf + (size_t)gr * N + gc) =
                    make_float2(acc[mf][nf][0] * outscale, acc[mf][nf][1] * outscale);
                *(float2*)(Cf + (size_t)(gr + 8) * N + gc) =
                    make_float2(acc[mf][nf][2] * outscale, acc[mf][nf][3] * outscale);
            }
        }
    }
}

// ---------------------------------------------------------------------------
// Attention v7 (R14 best): 256 threads = 8 warps x 16 q-rows, 64-key blocks,
// register softmax, raw-domain exp2, diagonal-only masking, warp block-skip,
// cp.async double-buffered K/V, heavy-first qt ordering.
// ---------------------------------------------------------------------------
#define AQH 0
#define AQL 16384
#define AKV 32768
#define A_SMEM (32768 + 2 * 32768)
#define EXP_C (0.125f / 65536.f * 1.4426950408889634f)

__global__ __launch_bounds__(256, 2) void attn_f16v7(
    const __half* __restrict__ qkvh, const __half* __restrict__ qkvl,
    __half* __restrict__ ath, __half* __restrict__ atl) {
    extern __shared__ char smc[];

    const int qt = 3 - blockIdx.x;   // heavy tiles first
    const int c  = blockIdx.y;
    const int h  = blockIdx.z;
    const int tid  = threadIdx.x;
    const int lane = tid & 31;
    const int w    = tid >> 5;

    const int q0 = qt * 128;
    const int qrow0 = c * WIN + q0;

    const int lm_row  = (lane & 7) + ((lane >> 3) & 1) * 8;
    const int lm_csel = lane >> 4;
    const int gs = (lane >> 4) & 1;
    const int gc2 = (lane >> 3) & 1;
    const uint32_t sb = (uint32_t)__cvta_generic_to_shared(smc);

    const int kb_start = (c == 0) ? (WIN / 64) : 0;
    const int kb_end = ((q0 + 127 + WIN) >> 6) + 1;

    auto issue_kv = [&](int kb, int buf) {
        const int jbase = c * WIN + kb * 64 - WIN;
        #pragma unroll
        for (int i = 0; i < 8; i++) {
            const int lin = tid + i * 256;
            const int pl  = lin >> 9;
            const int rem = lin & 511;
            const int row = rem >> 3;
            const int ch  = rem & 7;
            const __half* src = ((pl & 1) ? qkvl : qkvh)
                + (size_t)(jbase + row) * D3 + ((pl >> 1) ? 2 * DMODEL : DMODEL)
                + h * HDIM + ch * 8;
            const uint32_t dst = sb + AKV + buf * 32768 + pl * 8192 +
                                 row * 128 + ((ch ^ (row & 7)) << 4);
            CP_ASYNC16(dst, src);
        }
        CP_COMMIT();
    };

    // Q tile (128 rows, hi+lo), 256 threads
    #pragma unroll
    for (int i = 0; i < 8; i++) {
        const int lin = tid + i * 256;
        const int pl  = lin >> 10;
        const int rem = lin & 1023;
        const int row = rem >> 3;
        const int ch  = rem & 7;
        const __half* src = (pl ? qkvl : qkvh)
            + (size_t)(qrow0 + row) * D3 + h * HDIM + ch * 8;
        const uint4 v = *(const uint4*)src;
        *(uint4*)(smc + pl * 16384 + row * 128 + ((ch ^ (row & 7)) << 4)) = v;
    }
    issue_kv(kb_start, 0);

    float o[8][4] = {};
    float m0 = -3e38f, m1 = -3e38f, l0r = 0.f, l1r = 0.f;

    const int rq0 = q0 + w * 16 + (lane >> 2);
    const int rq1 = rq0 + 8;

    int buf = 0;
    for (int kb = kb_start; kb < kb_end; kb++) {
        const int j0 = kb * 64;
        CP_WAIT0();
        __syncthreads();
        if (kb + 1 < kb_end) issue_kv(kb + 1, buf ^ 1);

        if (j0 <= q0 + w * 16 + 15 + WIN) {
            const uint32_t kv = sb + AKV + buf * 32768;

            float s[8][4] = {};
            #pragma unroll
            for (int ks = 0; ks < 4; ks++) {
                uint32_t qH[4], qL[4];
                {
                    const int qr = w * 16 + lm_row;
                    const uint32_t off =
                        (uint32_t)(qr * 128 + (((2 * ks + lm_csel) ^ (qr & 7)) << 4));
                    LDSM_X4(qH[0], qH[1], qH[2], qH[3], sb + AQH + off);
                    LDSM_X4(qL[0], qL[1], qL[2], qL[3], sb + AQL + off);
                }
                #pragma unroll
                for (int p = 0; p < 4; p++) {
                    const int jr = 8 * (2 * p + gs) + (lane & 7);
                    const uint32_t off =
                        (uint32_t)(jr * 128 + (((2 * ks + gc2) ^ (jr & 7)) << 4));
                    uint32_t rH[4], rL[4];
                    LDSM_X4(rH[0], rH[1], rH[2], rH[3], kv + off);
                    LDSM_X4(rL[0], rL[1], rL[2], rL[3], kv + 8192 + off);
                    #pragma unroll
                    for (int s2 = 0; s2 < 2; s2++) {
                        const int nf = 2 * p + s2;
                        MMA_F16(s[nf], qH[0], qH[1], qH[2], qH[3], rH[2*s2], rH[2*s2+1]);
                        MMA_F16(s[nf], qH[0], qH[1], qH[2], qH[3], rL[2*s2], rL[2*s2+1]);
                        MMA_F16(s[nf], qL[0], qL[1], qL[2], qL[3], rH[2*s2], rH[2*s2+1]);
                    }
                }
            }

            if (j0 + 63 > q0 + w * 16 + WIN) {
                #pragma unroll
                for (int nf = 0; nf < 8; nf++) {
                    const int col = j0 + nf * 8 + 2 * (lane & 3);
                    if (rq0 + WIN < col)     s[nf][0] = -3e38f;
                    if (rq0 + WIN < col + 1) s[nf][1] = -3e38f;
                    if (rq1 + WIN < col)     s[nf][2] = -3e38f;
                    if (rq1 + WIN < col + 1) s[nf][3] = -3e38f;
                }
            }

            float mx0 = -3e38f, mx1 = -3e38f;
            #pragma unroll
            for (int nf = 0; nf < 8; nf++) {
                mx0 = fmaxf(mx0, fmaxf(s[nf][0], s[nf][1]));
                mx1 = fmaxf(mx1, fmaxf(s[nf][2], s[nf][3]));
            }
            mx0 = fmaxf(mx0, __shfl_xor_sync(0xffffffffu, mx0, 1));
            mx0 = fmaxf(mx0, __shfl_xor_sync(0xffffffffu, mx0, 2));
            mx1 = fmaxf(mx1, __shfl_xor_sync(0xffffffffu, mx1, 1));
            mx1 = fmaxf(mx1, __shfl_xor_sync(0xffffffffu, mx1, 2));
            const float m0n = fmaxf(m0, mx0);
            const float m1n = fmaxf(m1, mx1);
            const float a0 = fexp2((m0 - m0n) * EXP_C);
            const float a1 = fexp2((m1 - m1n) * EXP_C);
            const float b0 = m0n * EXP_C - 11.f;
            const float b1 = m1n * EXP_C - 11.f;
            float sum0 = 0.f, sum1 = 0.f;
            #pragma unroll
            for (int nf = 0; nf < 8; nf++) {
                s[nf][0] = fexp2(fmaf(s[nf][0], EXP_C, -b0));
                s[nf][1] = fexp2(fmaf(s[nf][1], EXP_C, -b0));
                s[nf][2] = fexp2(fmaf(s[nf][2], EXP_C, -b1));
                s[nf][3] = fexp2(fmaf(s[nf][3], EXP_C, -b1));
                sum0 += s[nf][0] + s[nf][1];
                sum1 += s[nf][2] + s[nf][3];
            }
            sum0 += __shfl_xor_sync(0xffffffffu, sum0, 1);
            sum0 += __shfl_xor_sync(0xffffffffu, sum0, 2);
            sum1 += __shfl_xor_sync(0xffffffffu, sum1, 1);
            sum1 += __shfl_xor_sync(0xffffffffu, sum1, 2);
            m0 = m0n; m1 = m1n;
            l0r = l0r * a0 + sum0;
            l1r = l1r * a1 + sum1;
            #pragma unroll
            for (int nf = 0; nf < 8; nf++) {
                o[nf][0] *= a0; o[nf][1] *= a0;
                o[nf][2] *= a1; o[nf][3] *= a1;
            }
            uint32_t pH[4][4], pL[4][4];
            #pragma unroll
            for (int ks = 0; ks < 4; ks++) {
                pH[ks][0] = split_pack(s[2*ks][0],   s[2*ks][1],   pL[ks][0]);
                pH[ks][1] = split_pack(s[2*ks][2],   s[2*ks][3],   pL[ks][1]);
                pH[ks][2] = split_pack(s[2*ks+1][0], s[2*ks+1][1], pL[ks][2]);
                pH[ks][3] = split_pack(s[2*ks+1][2], s[2*ks+1][3], pL[ks][3]);
            }

            #pragma unroll
            for (int ks = 0; ks < 4; ks++) {
                #pragma unroll
                for (int p2 = 0; p2 < 4; p2++) {
                    const int jr = 16 * ks + 8 * gc2 + (lane & 7);
                    const int ch = 2 * p2 + gs;
                    const uint32_t off =
                        (uint32_t)(jr * 128 + ((ch ^ (jr & 7)) << 4));
                    uint32_t rH[4], rL[4];
                    LDSM_X4_T(rH[0], rH[1], rH[2], rH[3], kv + 16384 + off);
                    LDSM_X4_T(rL[0], rL[1], rL[2], rL[3], kv + 24576 + off);
                    #pragma unroll
                    for (int s2 = 0; s2 < 2; s2++) {
                        const int nf = 2 * p2 + s2;
                        MMA_F16(o[nf], pH[ks][0], pH[ks][1], pH[ks][2], pH[ks][3], rH[2*s2], rH[2*s2+1]);
                        MMA_F16(o[nf], pH[ks][0], pH[ks][1], pH[ks][2], pH[ks][3], rL[2*s2], rL[2*s2+1]);
                        MMA_F16(o[nf], pL[ks][0], pL[ks][1], pL[ks][2], pL[ks][3], rH[2*s2], rH[2*s2+1]);
                    }
                }
            }
        }
        buf ^= 1;
    }

    const float inv0 = 1.f / l0r;
    const float inv1 = 1.f / l1r;
    const int grow0 = qrow0 + w * 16 + (lane >> 2);
    const int grow1 = grow0 + 8;
    #pragma unroll
    for (int nf = 0; nf < 8; nf++) {
        const int dcol = h * HDIM + nf * 8 + 2 * (lane & 3);
        uint32_t lo;
        uint32_t hi = split_pack(o[nf][0] * inv0, o[nf][1] * inv0, lo);
        *(uint32_t*)(ath + (size_t)grow0 * DMODEL + dcol) = hi;
        *(uint32_t*)(atl + (size_t)grow0 * DMODEL + dcol) = lo;
        hi = split_pack(o[nf][2] * inv1, o[nf][3] * inv1, lo);
        *(uint32_t*)(ath + (size_t)grow1 * DMODEL + dcol) = hi;
        *(uint32_t*)(atl + (size_t)grow1 * DMODEL + dcol) = lo;
    }
}

// ---------------------------------------------------------------------------
extern "C" void kernel_launch(void* const* d_in, const int* in_sizes, int n_in,
                              void* d_out, int out_size) {
    const float* x      = (const float*)d_in[0];
    const float* w_qkv  = (const float*)d_in[1];
    const float* w_out  = (const float*)d_in[2];
    float* out = (float*)d_out;

    __half *qkvh, *qkvl, *xh, *xl, *wqh, *wql, *ath, *atl, *woh, *wol;
    cudaGetSymbolAddress((void**)&qkvh, g_qkvh);
    cudaGetSymbolAddress((void**)&qkvl, g_qkvl);
    cudaGetSymbolAddress((void**)&xh, g_xh);
    cudaGetSymbolAddress((void**)&xl, g_xl);
    cudaGetSymbolAddress((void**)&wqh, g_wqh);
    cudaGetSymbolAddress((void**)&wql, g_wql);
    cudaGetSymbolAddress((void**)&ath, g_ath);
    cudaGetSymbolAddress((void**)&atl, g_atl);
    cudaGetSymbolAddress((void**)&woh, g_woh);
    cudaGetSymbolAddress((void**)&wol, g_wol);

    const int gemm_smem = 65536;
    cudaFuncSetAttribute(gemm_f16x3<true>, cudaFuncAttributeMaxDynamicSharedMemorySize,
                         gemm_smem);
    cudaFuncSetAttribute(gemm_f16x3<false>, cudaFuncAttributeMaxDynamicSharedMemorySize,
                         gemm_smem);
    cudaFuncSetAttribute(attn_f16v7, cudaFuncAttributeMaxDynamicSharedMemorySize,
                         A_SMEM);

    const int NX = SEQ * DMODEL;

    split2h<<<NX / 4 / 256, 256>>>(x, xh, xl, NX);
    split2h_t<<<dim3(D3 / 32, DMODEL / 32), dim3(32, 8)>>>(w_qkv, wqh, wql,
                                                           DMODEL, D3);
    gemm_f16x3<true><<<dim3(D3 / 128, SEQ / 128), 256, gemm_smem>>>(
        xh, xl, wqh, wql, nullptr, qkvh, qkvl, SEQ, D3, DMODEL, 1.f / 256.f);

    attn_f16v7<<<dim3(4, NCHUNK, NHEAD), 256, A_SMEM>>>(qkvh, qkvl, ath, atl);

    split2h_t<<<dim3(DMODEL / 32, DMODEL / 32), dim3(32, 8)>>>(w_out, woh, wol,
                                                               DMODEL, DMODEL);
    gemm_f16x3<false><<<dim3(DMODEL / 128, SEQ / 128), 256, gemm_smem>>>(
        ath, atl, woh, wol, out, nullptr, nullptr, SEQ, DMODEL, DMODEL,
        1.f / 65536.f);
}

// round 16
// speedup vs baseline: 1.0665x; 1.0665x over previous
#include <cuda_runtime.h>
#include <cuda_fp16.h>
#include <cstdint>

// Problem constants
#define SEQ    4096
#define DMODEL 1024
#define D3     3072
#define NHEAD  16
#define HDIM   64
#define WIN    512
#define NCHUNK 8

// Scratch (device globals: allocation-free per harness rules)
__device__ __half g_qkvh[SEQ * D3];           // qkv hi plane (x256)
__device__ __half g_qkvl[SEQ * D3];           // qkv lo plane
__device__ __half g_xh[SEQ * DMODEL];
__device__ __half g_xl[SEQ * DMODEL];
__device__ __half g_wqh[D3 * DMODEL];         // w_qkv^T planes [N][K]
__device__ __half g_wql[D3 * DMODEL];
__device__ __half g_ath[SEQ * DMODEL];        // attn split planes (x256)
__device__ __half g_atl[SEQ * DMODEL];
__device__ __half g_woh[DMODEL * DMODEL];     // w_out^T planes [N][K]
__device__ __half g_wol[DMODEL * DMODEL];

// ---------------------------------------------------------------------------
// helpers
// ---------------------------------------------------------------------------
__device__ __forceinline__ void split_h(float x, __half& hi, __half& lo) {
    hi = __float2half_rn(x);
    lo = __float2half_rn(x - __half2float(hi));
}
__device__ __forceinline__ uint32_t split_pack(float x, float y, uint32_t& lo) {
    __half2 h2 = __float22half2_rn(make_float2(x, y));
    float2 hf = __half22float2(h2);
    __half2 l2 = __float22half2_rn(make_float2(x - hf.x, y - hf.y));
    lo = *reinterpret_cast<uint32_t*>(&l2);
    return *reinterpret_cast<uint32_t*>(&h2);
}
__device__ __forceinline__ float fexp2(float x) {
    float r;
    asm("ex2.approx.f32 %0, %1;" : "=f"(r) : "f"(x));
    return r;
}

#define MMA_F16(d, a0, a1, a2, a3, b0, b1)                                     \
    asm volatile(                                                              \
        "mma.sync.aligned.m16n8k16.row.col.f32.f16.f16.f32 "                   \
        "{%0,%1,%2,%3}, {%4,%5,%6,%7}, {%8,%9}, {%0,%1,%2,%3};"                \
        : "+f"((d)[0]), "+f"((d)[1]), "+f"((d)[2]), "+f"((d)[3])               \
        : "r"(a0), "r"(a1), "r"(a2), "r"(a3), "r"(b0), "r"(b1))

#define LDSM_X4(r0, r1, r2, r3, addr)                                          \
    asm volatile("ldmatrix.sync.aligned.m8n8.x4.shared.b16 {%0,%1,%2,%3}, [%4];" \
        : "=r"(r0), "=r"(r1), "=r"(r2), "=r"(r3) : "r"(addr))

#define LDSM_X4_T(r0, r1, r2, r3, addr)                                        \
    asm volatile("ldmatrix.sync.aligned.m8n8.x4.trans.shared.b16 {%0,%1,%2,%3}, [%4];" \
        : "=r"(r0), "=r"(r1), "=r"(r2), "=r"(r3) : "r"(addr))

#define CP_ASYNC16(dst, src)                                                   \
    asm volatile("cp.async.cg.shared.global [%0], [%1], 16;"                   \
        :: "r"(dst), "l"(src))
#define CP_COMMIT()  asm volatile("cp.async.commit_group;" ::: "memory")
#define CP_WAIT0()   asm volatile("cp.async.wait_group 0;" ::: "memory")
#define CP_WAIT1()   asm volatile("cp.async.wait_group 1;" ::: "memory")

// ---------------------------------------------------------------------------
// Split kernels
// ---------------------------------------------------------------------------
__global__ __launch_bounds__(256) void split2h(const float* __restrict__ in,
                                               __half* __restrict__ hp,
                                               __half* __restrict__ lp, int n) {
    const int idx = (blockIdx.x * 256 + threadIdx.x) * 4;
    if (idx >= n) return;
    const float4 v = *(const float4*)(in + idx);
    uint32_t l0, l1;
    const uint32_t h0 = split_pack(v.x * 256.f, v.y * 256.f, l0);
    const uint32_t h1 = split_pack(v.z * 256.f, v.w * 256.f, l1);
    *(uint2*)(hp + idx) = make_uint2(h0, h1);
    *(uint2*)(lp + idx) = make_uint2(l0, l1);
}

__global__ void split2h_t(const float* __restrict__ w,
                          __half* __restrict__ th, __half* __restrict__ tl,
                          int Kd, int Nd) {
    __shared__ float tile[32][33];
    const int k0 = blockIdx.y * 32, n0 = blockIdx.x * 32;
    const int tx = threadIdx.x, ty = threadIdx.y;
    for (int r = ty; r < 32; r += 8)
        tile[r][tx] = w[(size_t)(k0 + r) * Nd + n0 + tx];
    __syncthreads();
    for (int r = ty; r < 32; r += 8) {
        __half h, l;
        split_h(tile[tx][r] * 256.f, h, l);
        const size_t o = (size_t)(n0 + r) * Kd + k0 + tx;
        th[o] = h; tl[o] = l;
    }
}

// ---------------------------------------------------------------------------
// 3xFP16 GEMM (m16n8k16). R16: 3-stage BK=32 cp.async ring, 2 groups in
// flight, ONE __syncthreads per k32 iteration.
// Stage s (32 KB) at s*32768: A-block 16 KB then B-block 16 KB. Each block:
// 128 rows x 128 B; row = [hi plane chunks 0-3 | lo plane chunks 4-7],
// swizzled chunk' = chunk ^ (row & 7). 96 KB total, 2 CTAs/SM.
// ---------------------------------------------------------------------------
template <bool SPLIT_OUT>
__global__ __launch_bounds__(256, 2) void gemm_f16x3(
    const __half* __restrict__ Ahg, const __half* __restrict__ Alg,
    const __half* __restrict__ Bhg, const __half* __restrict__ Blg,
    float* __restrict__ Cf, __half* __restrict__ Ch, __half* __restrict__ Cl,
    int M, int N, int K, float outscale) {
    extern __shared__ char smc[];

    const int tid  = threadIdx.x;
    const int lane = tid & 31;
    const int warp = tid >> 5;
    const int warp_m = warp >> 2;
    const int warp_n = warp & 3;

    const int m0 = blockIdx.y * 128;
    const int n0 = blockIdx.x * 128;

    const int lm_row  = (lane & 7) + ((lane >> 3) & 1) * 8;
    const int lm_csel = lane >> 4;
    const int gs  = lane >> 4;
    const int gc2 = (lane >> 3) & 1;

    float acc[4][4][4] = {};

    const uint32_t sb = (uint32_t)__cvta_generic_to_shared(smc);

    const __half* base0 = Ahg + (size_t)m0 * K;
    const __half* base1 = Alg + (size_t)m0 * K;
    const __half* base2 = Bhg + (size_t)n0 * K;
    const __half* base3 = Blg + (size_t)n0 * K;

    const int NIT = K >> 5;     // BK = 32

    // issue loads for k-iteration it into stage (it % 3)
    auto issue = [&](int it) {
        const int k0 = it << 5;
        const uint32_t stg = sb + (uint32_t)(it % 3) * 32768u;
        #pragma unroll
        for (int i = 0; i < 8; i++) {
            const int lin = tid + i * 256;     // 0..2047
            const int pl  = lin >> 9;          // 0:Ah 1:Al 2:Bh 3:Bl
            const int rem = lin & 511;
            const int row = rem >> 2;          // 0..127
            const int ch  = rem & 3;           // 0..3 within plane
            const __half* src =
                (pl == 0 ? base0 : pl == 1 ? base1 : pl == 2 ? base2 : base3)
                + (size_t)row * K + k0 + ch * 8;
            const int chunk = ((pl & 1) << 2) | ch;     // 0-3 hi, 4-7 lo
            const uint32_t dst = stg + (uint32_t)((pl >> 1) * 16384 +
                                 row * 128 + ((chunk ^ (row & 7)) << 4));
            CP_ASYNC16(dst, src);
        }
        CP_COMMIT();
    };

    issue(0);
    issue(1);
    for (int it = 0; it < NIT; it++) {
        if (it + 1 < NIT) CP_WAIT1(); else CP_WAIT0();
        __syncthreads();
        if (it + 2 < NIT) issue(it + 2);

        const uint32_t stg = sb + (uint32_t)(it % 3) * 32768u;
        #pragma unroll
        for (int s = 0; s < 2; s++) {
            uint32_t aH[4][4], aL[4][4];
            #pragma unroll
            for (int mf = 0; mf < 4; mf++) {
                const int m = warp_m * 64 + mf * 16 + lm_row;
                const uint32_t offH = (uint32_t)(m * 128 +
                    (((2 * s + lm_csel)     ^ (m & 7)) << 4));
                const uint32_t offL = (uint32_t)(m * 128 +
                    (((4 + 2 * s + lm_csel) ^ (m & 7)) << 4));
                LDSM_X4(aH[mf][0], aH[mf][1], aH[mf][2], aH[mf][3], stg + offH);
                LDSM_X4(aL[mf][0], aL[mf][1], aL[mf][2], aL[mf][3], stg + offL);
            }
            uint32_t bH[2][4], bL[2][4];
            #pragma unroll
            for (int p = 0; p < 2; p++) {
                const int n = warp_n * 32 + (2 * p + gs) * 8 + (lane & 7);
                const uint32_t offH = (uint32_t)(16384 + n * 128 +
                    (((2 * s + gc2)     ^ (n & 7)) << 4));
                const uint32_t offL = (uint32_t)(16384 + n * 128 +
                    (((4 + 2 * s + gc2) ^ (n & 7)) << 4));
                LDSM_X4(bH[p][0], bH[p][1], bH[p][2], bH[p][3], stg + offH);
                LDSM_X4(bL[p][0], bL[p][1], bL[p][2], bL[p][3], stg + offL);
            }
            #pragma unroll
            for (int p = 0; p < 2; p++)
                #pragma unroll
                for (int sub = 0; sub < 2; sub++) {
                    const int nf = 2 * p + sub;
                    const uint32_t bh0 = bH[p][2 * sub], bh1 = bH[p][2 * sub + 1];
                    const uint32_t bl0 = bL[p][2 * sub], bl1 = bL[p][2 * sub + 1];
                    #pragma unroll
                    for (int mf = 0; mf < 4; mf++) {
                        MMA_F16(acc[mf][nf], aH[mf][0], aH[mf][1], aH[mf][2], aH[mf][3], bh0, bh1);
                        MMA_F16(acc[mf][nf], aH[mf][0], aH[mf][1], aH[mf][2], aH[mf][3], bl0, bl1);
                        MMA_F16(acc[mf][nf], aL[mf][0], aL[mf][1], aL[mf][2], aL[mf][3], bh0, bh1);
                    }
                }
        }
    }

    const int row_in = lane >> 2;
    const int col_in = 2 * (lane & 3);
    #pragma unroll
    for (int mf = 0; mf < 4; mf++) {
        const int gr = m0 + warp_m * 64 + mf * 16 + row_in;
        #pragma unroll
        for (int nf = 0; nf < 4; nf++) {
            const int gc = n0 + warp_n * 32 + nf * 8 + col_in;
            if (SPLIT_OUT) {
                uint32_t lo;
                uint32_t hi = split_pack(acc[mf][nf][0] * outscale,
                                         acc[mf][nf][1] * outscale, lo);
                *(uint32_t*)(Ch + (size_t)gr * N + gc) = hi;
                *(uint32_t*)(Cl + (size_t)gr * N + gc) = lo;
                hi = split_pack(acc[mf][nf][2] * outscale,
                                acc[mf][nf][3] * outscale, lo);
                *(uint32_t*)(Ch + (size_t)(gr + 8) * N + gc) = hi;
                *(uint32_t*)(Cl + (size_t)(gr + 8) * N + gc) = lo;
            } else {
                *(float2*)(Cf + (size_t)gr * N + gc) =
                    make_float2(acc[mf][nf][0] * outscale, acc[mf][nf][1] * outscale);
                *(float2*)(Cf + (size_t)(gr + 8) * N + gc) =
                    make_float2(acc[mf][nf][2] * outscale, acc[mf][nf][3] * outscale);
            }
        }
    }
}

// ---------------------------------------------------------------------------
// Attention v7 (R14 best, unchanged): 256 threads = 8 warps x 16 q-rows,
// 64-key blocks, register softmax, raw-domain exp2, diagonal-only masking,
// warp block-skip, cp.async double-buffered K/V, heavy-first qt ordering.
// ---------------------------------------------------------------------------
#define AQH 0
#define AQL 16384
#define AKV 32768
#define A_SMEM (32768 + 2 * 32768)
#define EXP_C (0.125f / 65536.f * 1.4426950408889634f)

__global__ __launch_bounds__(256, 2) void attn_f16v7(
    const __half* __restrict__ qkvh, const __half* __restrict__ qkvl,
    __half* __restrict__ ath, __half* __restrict__ atl) {
    extern __shared__ char smc[];

    const int qt = 3 - blockIdx.x;   // heavy tiles first
    const int c  = blockIdx.y;
    const int h  = blockIdx.z;
    const int tid  = threadIdx.x;
    const int lane = tid & 31;
    const int w    = tid >> 5;

    const int q0 = qt * 128;
    const int qrow0 = c * WIN + q0;

    const int lm_row  = (lane & 7) + ((lane >> 3) & 1) * 8;
    const int lm_csel = lane >> 4;
    const int gs = (lane >> 4) & 1;
    const int gc2 = (lane >> 3) & 1;
    const uint32_t sb = (uint32_t)__cvta_generic_to_shared(smc);

    const int kb_start = (c == 0) ? (WIN / 64) : 0;
    const int kb_end = ((q0 + 127 + WIN) >> 6) + 1;

    auto issue_kv = [&](int kb, int buf) {
        const int jbase = c * WIN + kb * 64 - WIN;
        #pragma unroll
        for (int i = 0; i < 8; i++) {
            const int lin = tid + i * 256;
            const int pl  = lin >> 9;
            const int rem = lin & 511;
            const int row = rem >> 3;
            const int ch  = rem & 7;
            const __half* src = ((pl & 1) ? qkvl : qkvh)
                + (size_t)(jbase + row) * D3 + ((pl >> 1) ? 2 * DMODEL : DMODEL)
                + h * HDIM + ch * 8;
            const uint32_t dst = sb + AKV + buf * 32768 + pl * 8192 +
                                 row * 128 + ((ch ^ (row & 7)) << 4);
            CP_ASYNC16(dst, src);
        }
        CP_COMMIT();
    };

    #pragma unroll
    for (int i = 0; i < 8; i++) {
        const int lin = tid + i * 256;
        const int pl  = lin >> 10;
        const int rem = lin & 1023;
        const int row = rem >> 3;
        const int ch  = rem & 7;
        const __half* src = (pl ? qkvl : qkvh)
            + (size_t)(qrow0 + row) * D3 + h * HDIM + ch * 8;
        const uint4 v = *(const uint4*)src;
        *(uint4*)(smc + pl * 16384 + row * 128 + ((ch ^ (row & 7)) << 4)) = v;
    }
    issue_kv(kb_start, 0);

    float o[8][4] = {};
    float m0 = -3e38f, m1 = -3e38f, l0r = 0.f, l1r = 0.f;

    const int rq0 = q0 + w * 16 + (lane >> 2);
    const int rq1 = rq0 + 8;

    int buf = 0;
    for (int kb = kb_start; kb < kb_end; kb++) {
        const int j0 = kb * 64;
        CP_WAIT0();
        __syncthreads();
        if (kb + 1 < kb_end) issue_kv(kb + 1, buf ^ 1);

        if (j0 <= q0 + w * 16 + 15 + WIN) {
            const uint32_t kv = sb + AKV + buf * 32768;

            float s[8][4] = {};
            #pragma unroll
            for (int ks = 0; ks < 4; ks++) {
                uint32_t qH[4], qL[4];
                {
                    const int qr = w * 16 + lm_row;
                    const uint32_t off =
                        (uint32_t)(qr * 128 + (((2 * ks + lm_csel) ^ (qr & 7)) << 4));
                    LDSM_X4(qH[0], qH[1], qH[2], qH[3], sb + AQH + off);
                    LDSM_X4(qL[0], qL[1], qL[2], qL[3], sb + AQL + off);
                }
                #pragma unroll
                for (int p = 0; p < 4; p++) {
                    const int jr = 8 * (2 * p + gs) + (lane & 7);
                    const uint32_t off =
                        (uint32_t)(jr * 128 + (((2 * ks + gc2) ^ (jr & 7)) << 4));
                    uint32_t rH[4], rL[4];
                    LDSM_X4(rH[0], rH[1], rH[2], rH[3], kv + off);
                    LDSM_X4(rL[0], rL[1], rL[2], rL[3], kv + 8192 + off);
                    #pragma unroll
                    for (int s2 = 0; s2 < 2; s2++) {
                        const int nf = 2 * p + s2;
                        MMA_F16(s[nf], qH[0], qH[1], qH[2], qH[3], rH[2*s2], rH[2*s2+1]);
                        MMA_F16(s[nf], qH[0], qH[1], qH[2], qH[3], rL[2*s2], rL[2*s2+1]);
                        MMA_F16(s[nf], qL[0], qL[1], qL[2], qL[3], rH[2*s2], rH[2*s2+1]);
                    }
                }
            }

            if (j0 + 63 > q0 + w * 16 + WIN) {
                #pragma unroll
                for (int nf = 0; nf < 8; nf++) {
                    const int col = j0 + nf * 8 + 2 * (lane & 3);
                    if (rq0 + WIN < col)     s[nf][0] = -3e38f;
                    if (rq0 + WIN < col + 1) s[nf][1] = -3e38f;
                    if (rq1 + WIN < col)     s[nf][2] = -3e38f;
                    if (rq1 + WIN < col + 1) s[nf][3] = -3e38f;
                }
            }

            float mx0 = -3e38f, mx1 = -3e38f;
            #pragma unroll
            for (int nf = 0; nf < 8; nf++) {
                mx0 = fmaxf(mx0, fmaxf(s[nf][0], s[nf][1]));
                mx1 = fmaxf(mx1, fmaxf(s[nf][2], s[nf][3]));
            }
            mx0 = fmaxf(mx0, __shfl_xor_sync(0xffffffffu, mx0, 1));
            mx0 = fmaxf(mx0, __shfl_xor_sync(0xffffffffu, mx0, 2));
            mx1 = fmaxf(mx1, __shfl_xor_sync(0xffffffffu, mx1, 1));
            mx1 = fmaxf(mx1, __shfl_xor_sync(0xffffffffu, mx1, 2));
            const float m0n = fmaxf(m0, mx0);
            const float m1n = fmaxf(m1, mx1);
            const float a0 = fexp2((m0 - m0n) * EXP_C);
            const float a1 = fexp2((m1 - m1n) * EXP_C);
            const float b0 = m0n * EXP_C - 11.f;
            const float b1 = m1n * EXP_C - 11.f;
            float sum0 = 0.f, sum1 = 0.f;
            #pragma unroll
            for (int nf = 0; nf < 8; nf++) {
                s[nf][0] = fexp2(fmaf(s[nf][0], EXP_C, -b0));
                s[nf][1] = fexp2(fmaf(s[nf][1], EXP_C, -b0));
                s[nf][2] = fexp2(fmaf(s[nf][2], EXP_C, -b1));
                s[nf][3] = fexp2(fmaf(s[nf][3], EXP_C, -b1));
                sum0 += s[nf][0] + s[nf][1];
                sum1 += s[nf][2] + s[nf][3];
            }
            sum0 += __shfl_xor_sync(0xffffffffu, sum0, 1);
            sum0 += __shfl_xor_sync(0xffffffffu, sum0, 2);
            sum1 += __shfl_xor_sync(0xffffffffu, sum1, 1);
            sum1 += __shfl_xor_sync(0xffffffffu, sum1, 2);
            m0 = m0n; m1 = m1n;
            l0r = l0r * a0 + sum0;
            l1r = l1r * a1 + sum1;
            #pragma unroll
            for (int nf = 0; nf < 8; nf++) {
                o[nf][0] *= a0; o[nf][1] *= a0;
                o[nf][2] *= a1; o[nf][3] *= a1;
            }
            uint32_t pH[4][4], pL[4][4];
            #pragma unroll
            for (int ks = 0; ks < 4; ks++) {
                pH[ks][0] = split_pack(s[2*ks][0],   s[2*ks][1],   pL[ks][0]);
                pH[ks][1] = split_pack(s[2*ks][2],   s[2*ks][3],   pL[ks][1]);
                pH[ks][2] = split_pack(s[2*ks+1][0], s[2*ks+1][1], pL[ks][2]);
                pH[ks][3] = split_pack(s[2*ks+1][2], s[2*ks+1][3], pL[ks][3]);
            }

            #pragma unroll
            for (int ks = 0; ks < 4; ks++) {
                #pragma unroll
                for (int p2 = 0; p2 < 4; p2++) {
                    const int jr = 16 * ks + 8 * gc2 + (lane & 7);
                    const int ch = 2 * p2 + gs;
                    const uint32_t off =
                        (uint32_t)(jr * 128 + ((ch ^ (jr & 7)) << 4));
                    uint32_t rH[4], rL[4];
                    LDSM_X4_T(rH[0], rH[1], rH[2], rH[3], kv + 16384 + off);
                    LDSM_X4_T(rL[0], rL[1], rL[2], rL[3], kv + 24576 + off);
                    #pragma unroll
                    for (int s2 = 0; s2 < 2; s2++) {
                        const int nf = 2 * p2 + s2;
                        MMA_F16(o[nf], pH[ks][0], pH[ks][1], pH[ks][2], pH[ks][3], rH[2*s2], rH[2*s2+1]);
                        MMA_F16(o[nf], pH[ks][0], pH[ks][1], pH[ks][2], pH[ks][3], rL[2*s2], rL[2*s2+1]);
                        MMA_F16(o[nf], pL[ks][0], pL[ks][1], pL[ks][2], pL[ks][3], rH[2*s2], rH[2*s2+1]);
                    }
                }
            }
        }
        buf ^= 1;
    }

    const float inv0 = 1.f / l0r;
    const float inv1 = 1.f / l1r;
    const int grow0 = qrow0 + w * 16 + (lane >> 2);
    const int grow1 = grow0 + 8;
    #pragma unroll
    for (int nf = 0; nf < 8; nf++) {
        const int dcol = h * HDIM + nf * 8 + 2 * (lane & 3);
        uint32_t lo;
        uint32_t hi = split_pack(o[nf][0] * inv0, o[nf][1] * inv0, lo);
        *(uint32_t*)(ath + (size_t)grow0 * DMODEL + dcol) = hi;
        *(uint32_t*)(atl + (size_t)grow0 * DMODEL + dcol) = lo;
        hi = split_pack(o[nf][2] * inv1, o[nf][3] * inv1, lo);
        *(uint32_t*)(ath + (size_t)grow1 * DMODEL + dcol) = hi;
        *(uint32_t*)(atl + (size_t)grow1 * DMODEL + dcol) = lo;
    }
}

// ---------------------------------------------------------------------------
extern "C" void kernel_launch(void* const* d_in, const int* in_sizes, int n_in,
                              void* d_out, int out_size) {
    const float* x      = (const float*)d_in[0];
    const float* w_qkv  = (const float*)d_in[1];
    const float* w_out  = (const float*)d_in[2];
    float* out = (float*)d_out;

    __half *qkvh, *qkvl, *xh, *xl, *wqh, *wql, *ath, *atl, *woh, *wol;
    cudaGetSymbolAddress((void**)&qkvh, g_qkvh);
    cudaGetSymbolAddress((void**)&qkvl, g_qkvl);
    cudaGetSymbolAddress((void**)&xh, g_xh);
    cudaGetSymbolAddress((void**)&xl, g_xl);
    cudaGetSymbolAddress((void**)&wqh, g_wqh);
    cudaGetSymbolAddress((void**)&wql, g_wql);
    cudaGetSymbolAddress((void**)&ath, g_ath);
    cudaGetSymbolAddress((void**)&atl, g_atl);
    cudaGetSymbolAddress((void**)&woh, g_woh);
    cudaGetSymbolAddress((void**)&wol, g_wol);

    const int gemm_smem = 98304;   // 3 stages x 32 KB
    cudaFuncSetAttribute(gemm_f16x3<true>, cudaFuncAttributeMaxDynamicSharedMemorySize,
                         gemm_smem);
    cudaFuncSetAttribute(gemm_f16x3<false>, cudaFuncAttributeMaxDynamicSharedMemorySize,
                         gemm_smem);
    cudaFuncSetAttribute(attn_f16v7, cudaFuncAttributeMaxDynamicSharedMemorySize,
                         A_SMEM);

    const int NX = SEQ * DMODEL;

    split2h<<<NX / 4 / 256, 256>>>(x, xh, xl, NX);
    split2h_t<<<dim3(D3 / 32, DMODEL / 32), dim3(32, 8)>>>(w_qkv, wqh, wql,
                                                           DMODEL, D3);
    gemm_f16x3<true><<<dim3(D3 / 128, SEQ / 128), 256, gemm_smem>>>(
        xh, xl, wqh, wql, nullptr, qkvh, qkvl, SEQ, D3, DMODEL, 1.f / 256.f);

    attn_f16v7<<<dim3(4, NCHUNK, NHEAD), 256, A_SMEM>>>(qkvh, qkvl, ath, atl);

    split2h_t<<<dim3(DMODEL / 32, DMODEL / 32), dim3(32, 8)>>>(w_out, woh, wol,
                                                               DMODEL, DMODEL);
    gemm_f16x3<false><<<dim3(DMODEL / 128, SEQ / 128), 256, gemm_smem>>>(
        ath, atl, woh, wol, out, nullptr, nullptr, SEQ, DMODEL, DMODEL,
        1.f / 65536.f);
}

// round 17
// speedup vs baseline: 1.1345x; 1.0638x over previous
#include <cuda_runtime.h>
#include <cuda_fp16.h>
#include <cstdint>

// Problem constants
#define SEQ    4096
#define DMODEL 1024
#define D3     3072
#define NHEAD  16
#define HDIM   64
#define WIN    512
#define NCHUNK 8

// Scratch (device globals: allocation-free per harness rules)
__device__ __half g_qkvh[SEQ * D3];           // qkv hi plane (x256)
__device__ __half g_qkvl[SEQ * D3];           // qkv lo plane
__device__ __half g_xh[SEQ * DMODEL];
__device__ __half g_xl[SEQ * DMODEL];
__device__ __half g_wqh[D3 * DMODEL];         // w_qkv^T planes [N][K]
__device__ __half g_wql[D3 * DMODEL];
__device__ __half g_ath[SEQ * DMODEL];        // attn split planes (x256)
__device__ __half g_atl[SEQ * DMODEL];
__device__ __half g_woh[DMODEL * DMODEL];     // w_out^T planes [N][K]
__device__ __half g_wol[DMODEL * DMODEL];

// ---------------------------------------------------------------------------
// helpers
// ---------------------------------------------------------------------------
__device__ __forceinline__ void split_h(float x, __half& hi, __half& lo) {
    hi = __float2half_rn(x);
    lo = __float2half_rn(x - __half2float(hi));
}
__device__ __forceinline__ uint32_t split_pack(float x, float y, uint32_t& lo) {
    __half2 h2 = __float22half2_rn(make_float2(x, y));
    float2 hf = __half22float2(h2);
    __half2 l2 = __float22half2_rn(make_float2(x - hf.x, y - hf.y));
    lo = *reinterpret_cast<uint32_t*>(&l2);
    return *reinterpret_cast<uint32_t*>(&h2);
}
__device__ __forceinline__ float fexp2(float x) {
    float r;
    asm("ex2.approx.f32 %0, %1;" : "=f"(r) : "f"(x));
    return r;
}

#define MMA_F16(d, a0, a1, a2, a3, b0, b1)                                     \
    asm volatile(                                                              \
        "mma.sync.aligned.m16n8k16.row.col.f32.f16.f16.f32 "                   \
        "{%0,%1,%2,%3}, {%4,%5,%6,%7}, {%8,%9}, {%0,%1,%2,%3};"                \
        : "+f"((d)[0]), "+f"((d)[1]), "+f"((d)[2]), "+f"((d)[3])               \
        : "r"(a0), "r"(a1), "r"(a2), "r"(a3), "r"(b0), "r"(b1))

#define LDSM_X4(r0, r1, r2, r3, addr)                                          \
    asm volatile("ldmatrix.sync.aligned.m8n8.x4.shared.b16 {%0,%1,%2,%3}, [%4];" \
        : "=r"(r0), "=r"(r1), "=r"(r2), "=r"(r3) : "r"(addr))

#define LDSM_X4_T(r0, r1, r2, r3, addr)                                        \
    asm volatile("ldmatrix.sync.aligned.m8n8.x4.trans.shared.b16 {%0,%1,%2,%3}, [%4];" \
        : "=r"(r0), "=r"(r1), "=r"(r2), "=r"(r3) : "r"(addr))

#define CP_ASYNC16(dst, src)                                                   \
    asm volatile("cp.async.cg.shared.global [%0], [%1], 16;"                   \
        :: "r"(dst), "l"(src))
#define CP_COMMIT()  asm volatile("cp.async.commit_group;" ::: "memory")
#define CP_WAIT0()   asm volatile("cp.async.wait_group 0;" ::: "memory")

// ---------------------------------------------------------------------------
// Fused prep kernel: one launch performs all three splits.
//   blocks [0, 4096)        : x split           (flat, 4 floats/thread)
//   blocks [4096, 7168)     : w_qkv T-split     (32x32 tiles, 96 x 32 grid)
//   blocks [7168, 8192)     : w_out T-split     (32x32 tiles, 32 x 32 grid)
// ---------------------------------------------------------------------------
__global__ __launch_bounds__(256) void prep_all(
    const float* __restrict__ x,
    const float* __restrict__ w_qkv,
    const float* __restrict__ w_out,
    __half* __restrict__ xh, __half* __restrict__ xl,
    __half* __restrict__ wqh, __half* __restrict__ wql,
    __half* __restrict__ woh, __half* __restrict__ wol) {
    const int bid = blockIdx.x;
    const int tid = threadIdx.x;

    if (bid < 4096) {
        const int idx = (bid * 256 + tid) * 4;
        const float4 v = *(const float4*)(x + idx);
        uint32_t l0, l1;
        const uint32_t h0 = split_pack(v.x * 256.f, v.y * 256.f, l0);
        const uint32_t h1 = split_pack(v.z * 256.f, v.w * 256.f, l1);
        *(uint2*)(xh + idx) = make_uint2(h0, h1);
        *(uint2*)(xl + idx) = make_uint2(l0, l1);
        return;
    }

    // transpose-split path
    __shared__ float tile[32][33];
    const float* w;
    __half *th, *tl;
    int Kd, Nd, bx, by;
    if (bid < 7168) {
        const int r = bid - 4096;          // 0..3071
        w = w_qkv; th = wqh; tl = wql; Kd = DMODEL; Nd = D3;
        bx = r % 96; by = r / 96;          // (96, 32)
    } else {
        const int r = bid - 7168;          // 0..1023
        w = w_out; th = woh; tl = wol; Kd = DMODEL; Nd = DMODEL;
        bx = r % 32; by = r / 32;          // (32, 32)
    }
    const int k0 = by * 32, n0 = bx * 32;
    const int tx = tid & 31, ty = tid >> 5;   // 32 x 8
    for (int r = ty; r < 32; r += 8)
        tile[r][tx] = w[(size_t)(k0 + r) * Nd + n0 + tx];
    __syncthreads();
    for (int r = ty; r < 32; r += 8) {
        __half h, l;
        split_h(tile[tx][r] * 256.f, h, l);
        const size_t o = (size_t)(n0 + r) * Kd + k0 + tx;
        th[o] = h; tl[o] = l;
    }
}

// ---------------------------------------------------------------------------
// 3xFP16 GEMM (m16n8k16) — R14 version: 2-stage BK=32 cp.async ring
// interleaved in the chunk dimension, ldmatrix B fragments. 64 KB, 2 CTAs/SM.
// ---------------------------------------------------------------------------
template <bool SPLIT_OUT>
__global__ __launch_bounds__(256, 2) void gemm_f16x3(
    const __half* __restrict__ Ahg, const __half* __restrict__ Alg,
    const __half* __restrict__ Bhg, const __half* __restrict__ Blg,
    float* __restrict__ Cf, __half* __restrict__ Ch, __half* __restrict__ Cl,
    int M, int N, int K, float outscale) {
    extern __shared__ char smc[];

    const int tid  = threadIdx.x;
    const int lane = tid & 31;
    const int warp = tid >> 5;
    const int warp_m = warp >> 2;
    const int warp_n = warp & 3;

    const int m0 = blockIdx.y * 128;
    const int n0 = blockIdx.x * 128;

    const int lm_row  = (lane & 7) + ((lane >> 3) & 1) * 8;
    const int lm_csel = lane >> 4;
    const int gs  = lane >> 4;
    const int gc2 = (lane >> 3) & 1;

    float acc[4][4][4] = {};

    const uint32_t sb = (uint32_t)__cvta_generic_to_shared(smc);

    const __half* base0 = Ahg + (size_t)m0 * K;
    const __half* base1 = Alg + (size_t)m0 * K;
    const __half* base2 = Bhg + (size_t)n0 * K;
    const __half* base3 = Blg + (size_t)n0 * K;

    const int NIT = K >> 5;

    auto issue = [&](int it) {
        const int k0 = it << 5;
        const int st4 = (it & 1) << 2;
        #pragma unroll
        for (int i = 0; i < 8; i++) {
            const int lin = tid + i * 256;
            const int pl  = lin >> 9;
            const int rem = lin & 511;
            const int row = rem >> 2;
            const int ch  = rem & 3;
            const __half* src =
                (pl == 0 ? base0 : pl == 1 ? base1 : pl == 2 ? base2 : base3)
                + (size_t)row * K + k0 + ch * 8;
            const uint32_t dst = sb + pl * 16384 + row * 128 +
                                 (((st4 + ch) ^ (row & 7)) << 4);
            CP_ASYNC16(dst, src);
        }
        CP_COMMIT();
    };

    issue(0);
    for (int it = 0; it < NIT; it++) {
        CP_WAIT0();
        __syncthreads();
        if (it + 1 < NIT) issue(it + 1);

        const int st4 = (it & 1) << 2;
        #pragma unroll
        for (int s = 0; s < 2; s++) {
            const int c0 = st4 + 2 * s;
            uint32_t aH[4][4], aL[4][4];
            #pragma unroll
            for (int mf = 0; mf < 4; mf++) {
                const int m = warp_m * 64 + mf * 16 + lm_row;
                const uint32_t off =
                    (uint32_t)(m * 128 + (((c0 + lm_csel) ^ (m & 7)) << 4));
                LDSM_X4(aH[mf][0], aH[mf][1], aH[mf][2], aH[mf][3], sb + off);
                LDSM_X4(aL[mf][0], aL[mf][1], aL[mf][2], aL[mf][3], sb + 16384 + off);
            }
            uint32_t bH[2][4], bL[2][4];
            #pragma unroll
            for (int p = 0; p < 2; p++) {
                const int n = warp_n * 32 + (2 * p + gs) * 8 + (lane & 7);
                const uint32_t off =
                    (uint32_t)(n * 128 + (((c0 + gc2) ^ (n & 7)) << 4));
                LDSM_X4(bH[p][0], bH[p][1], bH[p][2], bH[p][3], sb + 32768 + off);
                LDSM_X4(bL[p][0], bL[p][1], bL[p][2], bL[p][3], sb + 49152 + off);
            }
            #pragma unroll
            for (int p = 0; p < 2; p++)
                #pragma unroll
                for (int sub = 0; sub < 2; sub++) {
                    const int nf = 2 * p + sub;
                    const uint32_t bh0 = bH[p][2 * sub], bh1 = bH[p][2 * sub + 1];
                    const uint32_t bl0 = bL[p][2 * sub], bl1 = bL[p][2 * sub + 1];
                    #pragma unroll
                    for (int mf = 0; mf < 4; mf++) {
                        MMA_F16(acc[mf][nf], aH[mf][0], aH[mf][1], aH[mf][2], aH[mf][3], bh0, bh1);
                        MMA_F16(acc[mf][nf], aH[mf][0], aH[mf][1], aH[mf][2], aH[mf][3], bl0, bl1);
                        MMA_F16(acc[mf][nf], aL[mf][0], aL[mf][1], aL[mf][2], aL[mf][3], bh0, bh1);
                    }
                }
        }
        __syncthreads();
    }

    const int row_in = lane >> 2;
    const int col_in = 2 * (lane & 3);
    #pragma unroll
    for (int mf = 0; mf < 4; mf++) {
        const int gr = m0 + warp_m * 64 + mf * 16 + row_in;
        #pragma unroll
        for (int nf = 0; nf < 4; nf++) {
            const int gc = n0 + warp_n * 32 + nf * 8 + col_in;
            if (SPLIT_OUT) {
                uint32_t lo;
                uint32_t hi = split_pack(acc[mf][nf][0] * outscale,
                                         acc[mf][nf][1] * outscale, lo);
                *(uint32_t*)(Ch + (size_t)gr * N + gc) = hi;
                *(uint32_t*)(Cl + (size_t)gr * N + gc) = lo;
                hi = split_pack(acc[mf][nf][2] * outscale,
                                acc[mf][nf][3] * outscale, lo);
                *(uint32_t*)(Ch + (size_t)(gr + 8) * N + gc) = hi;
                *(uint32_t*)(Cl + (size_t)(gr + 8) * N + gc) = lo;
            } else {
                *(float2*)(Cf + (size_t)gr * N + gc) =
                    make_float2(acc[mf][nf][0] * outscale, acc[mf][nf][1] * outscale);
                *(float2*)(Cf + (size_t)(gr + 8) * N + gc) =
                    make_float2(acc[mf][nf][2] * outscale, acc[mf][nf][3] * outscale);
            }
        }
    }
}

// ---------------------------------------------------------------------------
// Attention v8: R14 kernel with a 1D grid globally sorted by descending work
// (LPT-style): ids [0,448) = qt 3..0 with c>=1 (112 each); ids [448,512) =
// qt 3..0 with c==0 (16 each). Wave-2 work stealing backfills light CTAs.
// ---------------------------------------------------------------------------
#define AQH 0
#define AQL 16384
#define AKV 32768
#define A_SMEM (32768 + 2 * 32768)
#define EXP_C (0.125f / 65536.f * 1.4426950408889634f)

__global__ __launch_bounds__(256, 2) void attn_f16v8(
    const __half* __restrict__ qkvh, const __half* __restrict__ qkvl,
    __half* __restrict__ ath, __half* __restrict__ atl) {
    extern __shared__ char smc[];

    // ---- sorted work decode ----
    int qt, c, h;
    {
        const int id = blockIdx.x;
        if (id < 448) {
            qt = 3 - (id / 112);
            const int r = id % 112;
            c = 1 + (r >> 4);
            h = r & 15;
        } else {
            const int e = id - 448;
            qt = 3 - (e >> 4);
            c = 0;
            h = e & 15;
        }
    }

    const int tid  = threadIdx.x;
    const int lane = tid & 31;
    const int w    = tid >> 5;

    const int q0 = qt * 128;
    const int qrow0 = c * WIN + q0;

    const int lm_row  = (lane & 7) + ((lane >> 3) & 1) * 8;
    const int lm_csel = lane >> 4;
    const int gs = (lane >> 4) & 1;
    const int gc2 = (lane >> 3) & 1;
    const uint32_t sb = (uint32_t)__cvta_generic_to_shared(smc);

    const int kb_start = (c == 0) ? (WIN / 64) : 0;
    const int kb_end = ((q0 + 127 + WIN) >> 6) + 1;

    auto issue_kv = [&](int kb, int buf) {
        const int jbase = c * WIN + kb * 64 - WIN;
        #pragma unroll
        for (int i = 0; i < 8; i++) {
            const int lin = tid + i * 256;
            const int pl  = lin >> 9;
            const int rem = lin & 511;
            const int row = rem >> 3;
            const int ch  = rem & 7;
            const __half* src = ((pl & 1) ? qkvl : qkvh)
                + (size_t)(jbase + row) * D3 + ((pl >> 1) ? 2 * DMODEL : DMODEL)
                + h * HDIM + ch * 8;
            const uint32_t dst = sb + AKV + buf * 32768 + pl * 8192 +
                                 row * 128 + ((ch ^ (row & 7)) << 4);
            CP_ASYNC16(dst, src);
        }
        CP_COMMIT();
    };

    #pragma unroll
    for (int i = 0; i < 8; i++) {
        const int lin = tid + i * 256;
        const int pl  = lin >> 10;
        const int rem = lin & 1023;
        const int row = rem >> 3;
        const int ch  = rem & 7;
        const __half* src = (pl ? qkvl : qkvh)
            + (size_t)(qrow0 + row) * D3 + h * HDIM + ch * 8;
        const uint4 v = *(const uint4*)src;
        *(uint4*)(smc + pl * 16384 + row * 128 + ((ch ^ (row & 7)) << 4)) = v;
    }
    issue_kv(kb_start, 0);

    float o[8][4] = {};
    float m0 = -3e38f, m1 = -3e38f, l0r = 0.f, l1r = 0.f;

    const int rq0 = q0 + w * 16 + (lane >> 2);
    const int rq1 = rq0 + 8;

    int buf = 0;
    for (int kb = kb_start; kb < kb_end; kb++) {
        const int j0 = kb * 64;
        CP_WAIT0();
        __syncthreads();
        if (kb + 1 < kb_end) issue_kv(kb + 1, buf ^ 1);

        if (j0 <= q0 + w * 16 + 15 + WIN) {
            const uint32_t kv = sb + AKV + buf * 32768;

            float s[8][4] = {};
            #pragma unroll
            for (int ks = 0; ks < 4; ks++) {
                uint32_t qH[4], qL[4];
                {
                    const int qr = w * 16 + lm_row;
                    const uint32_t off =
                        (uint32_t)(qr * 128 + (((2 * ks + lm_csel) ^ (qr & 7)) << 4));
                    LDSM_X4(qH[0], qH[1], qH[2], qH[3], sb + AQH + off);
                    LDSM_X4(qL[0], qL[1], qL[2], qL[3], sb + AQL + off);
                }
                #pragma unroll
                for (int p = 0; p < 4; p++) {
                    const int jr = 8 * (2 * p + gs) + (lane & 7);
                    const uint32_t off =
                        (uint32_t)(jr * 128 + (((2 * ks + gc2) ^ (jr & 7)) << 4));
                    uint32_t rH[4], rL[4];
                    LDSM_X4(rH[0], rH[1], rH[2], rH[3], kv + off);
                    LDSM_X4(rL[0], rL[1], rL[2], rL[3], kv + 8192 + off);
                    #pragma unroll
                    for (int s2 = 0; s2 < 2; s2++) {
                        const int nf = 2 * p + s2;
                        MMA_F16(s[nf], qH[0], qH[1], qH[2], qH[3], rH[2*s2], rH[2*s2+1]);
                        MMA_F16(s[nf], qH[0], qH[1], qH[2], qH[3], rL[2*s2], rL[2*s2+1]);
                        MMA_F16(s[nf], qL[0], qL[1], qL[2], qL[3], rH[2*s2], rH[2*s2+1]);
                    }
                }
            }

            if (j0 + 63 > q0 + w * 16 + WIN) {
                #pragma unroll
                for (int nf = 0; nf < 8; nf++) {
                    const int col = j0 + nf * 8 + 2 * (lane & 3);
                    if (rq0 + WIN < col)     s[nf][0] = -3e38f;
                    if (rq0 + WIN < col + 1) s[nf][1] = -3e38f;
                    if (rq1 + WIN < col)     s[nf][2] = -3e38f;
                    if (rq1 + WIN < col + 1) s[nf][3] = -3e38f;
                }
            }

            float mx0 = -3e38f, mx1 = -3e38f;
            #pragma unroll
            for (int nf = 0; nf < 8; nf++) {
                mx0 = fmaxf(mx0, fmaxf(s[nf][0], s[nf][1]));
                mx1 = fmaxf(mx1, fmaxf(s[nf][2], s[nf][3]));
            }
            mx0 = fmaxf(mx0, __shfl_xor_sync(0xffffffffu, mx0, 1));
            mx0 = fmaxf(mx0, __shfl_xor_sync(0xffffffffu, mx0, 2));
            mx1 = fmaxf(mx1, __shfl_xor_sync(0xffffffffu, mx1, 1));
            mx1 = fmaxf(mx1, __shfl_xor_sync(0xffffffffu, mx1, 2));
            const float m0n = fmaxf(m0, mx0);
            const float m1n = fmaxf(m1, mx1);
            const float a0 = fexp2((m0 - m0n) * EXP_C);
            const float a1 = fexp2((m1 - m1n) * EXP_C);
            const float b0 = m0n * EXP_C - 11.f;
            const float b1 = m1n * EXP_C - 11.f;
            float sum0 = 0.f, sum1 = 0.f;
            #pragma unroll
            for (int nf = 0; nf < 8; nf++) {
                s[nf][0] = fexp2(fmaf(s[nf][0], EXP_C, -b0));
                s[nf][1] = fexp2(fmaf(s[nf][1], EXP_C, -b0));
                s[nf][2] = fexp2(fmaf(s[nf][2], EXP_C, -b1));
                s[nf][3] = fexp2(fmaf(s[nf][3], EXP_C, -b1));
                sum0 += s[nf][0] + s[nf][1];
                sum1 += s[nf][2] + s[nf][3];
            }
            sum0 += __shfl_xor_sync(0xffffffffu, sum0, 1);
            sum0 += __shfl_xor_sync(0xffffffffu, sum0, 2);
            sum1 += __shfl_xor_sync(0xffffffffu, sum1, 1);
            sum1 += __shfl_xor_sync(0xffffffffu, sum1, 2);
            m0 = m0n; m1 = m1n;
            l0r = l0r * a0 + sum0;
            l1r = l1r * a1 + sum1;
            #pragma unroll
            for (int nf = 0; nf < 8; nf++) {
                o[nf][0] *= a0; o[nf][1] *= a0;
                o[nf][2] *= a1; o[nf][3] *= a1;
            }
            uint32_t pH[4][4], pL[4][4];
            #pragma unroll
            for (int ks = 0; ks < 4; ks++) {
                pH[ks][0] = split_pack(s[2*ks][0],   s[2*ks][1],   pL[ks][0]);
                pH[ks][1] = split_pack(s[2*ks][2],   s[2*ks][3],   pL[ks][1]);
                pH[ks][2] = split_pack(s[2*ks+1][0], s[2*ks+1][1], pL[ks][2]);
                pH[ks][3] = split_pack(s[2*ks+1][2], s[2*ks+1][3], pL[ks][3]);
            }

            #pragma unroll
            for (int ks = 0; ks < 4; ks++) {
                #pragma unroll
                for (int p2 = 0; p2 < 4; p2++) {
                    const int jr = 16 * ks + 8 * gc2 + (lane & 7);
                    const int ch = 2 * p2 + gs;
                    const uint32_t off =
                        (uint32_t)(jr * 128 + ((ch ^ (jr & 7)) << 4));
                    uint32_t rH[4], rL[4];
                    LDSM_X4_T(rH[0], rH[1], rH[2], rH[3], kv + 16384 + off);
                    LDSM_X4_T(rL[0], rL[1], rL[2], rL[3], kv + 24576 + off);
                    #pragma unroll
                    for (int s2 = 0; s2 < 2; s2++) {
                        const int nf = 2 * p2 + s2;
                        MMA_F16(o[nf], pH[ks][0], pH[ks][1], pH[ks][2], pH[ks][3], rH[2*s2], rH[2*s2+1]);
                        MMA_F16(o[nf], pH[ks][0], pH[ks][1], pH[ks][2], pH[ks][3], rL[2*s2], rL[2*s2+1]);
                        MMA_F16(o[nf], pL[ks][0], pL[ks][1], pL[ks][2], pL[ks][3], rH[2*s2], rH[2*s2+1]);
                    }
                }
            }
        }
        buf ^= 1;
    }

    const float inv0 = 1.f / l0r;
    const float inv1 = 1.f / l1r;
    const int grow0 = qrow0 + w * 16 + (lane >> 2);
    const int grow1 = grow0 + 8;
    #pragma unroll
    for (int nf = 0; nf < 8; nf++) {
        const int dcol = h * HDIM + nf * 8 + 2 * (lane & 3);
        uint32_t lo;
        uint32_t hi = split_pack(o[nf][0] * inv0, o[nf][1] * inv0, lo);
        *(uint32_t*)(ath + (size_t)grow0 * DMODEL + dcol) = hi;
        *(uint32_t*)(atl + (size_t)grow0 * DMODEL + dcol) = lo;
        hi = split_pack(o[nf][2] * inv1, o[nf][3] * inv1, lo);
        *(uint32_t*)(ath + (size_t)grow1 * DMODEL + dcol) = hi;
        *(uint32_t*)(atl + (size_t)grow1 * DMODEL + dcol) = lo;
    }
}

// ---------------------------------------------------------------------------
extern "C" void kernel_launch(void* const* d_in, const int* in_sizes, int n_in,
                              void* d_out, int out_size) {
    const float* x      = (const float*)d_in[0];
    const float* w_qkv  = (const float*)d_in[1];
    const float* w_out  = (const float*)d_in[2];
    float* out = (float*)d_out;

    __half *qkvh, *qkvl, *xh, *xl, *wqh, *wql, *ath, *atl, *woh, *wol;
    cudaGetSymbolAddress((void**)&qkvh, g_qkvh);
    cudaGetSymbolAddress((void**)&qkvl, g_qkvl);
    cudaGetSymbolAddress((void**)&xh, g_xh);
    cudaGetSymbolAddress((void**)&xl, g_xl);
    cudaGetSymbolAddress((void**)&wqh, g_wqh);
    cudaGetSymbolAddress((void**)&wql, g_wql);
    cudaGetSymbolAddress((void**)&ath, g_ath);
    cudaGetSymbolAddress((void**)&atl, g_atl);
    cudaGetSymbolAddress((void**)&woh, g_woh);
    cudaGetSymbolAddress((void**)&wol, g_wol);

    const int gemm_smem = 65536;
    cudaFuncSetAttribute(gemm_f16x3<true>, cudaFuncAttributeMaxDynamicSharedMemorySize,
                         gemm_smem);
    cudaFuncSetAttribute(gemm_f16x3<false>, cudaFuncAttributeMaxDynamicSharedMemorySize,
                         gemm_smem);
    cudaFuncSetAttribute(attn_f16v8, cudaFuncAttributeMaxDynamicSharedMemorySize,
                         A_SMEM);

    // fused prep: x split + both weight transpose-splits in one launch
    prep_all<<<8192, 256>>>(x, w_qkv, w_out, xh, xl, wqh, wql, woh, wol);

    // 1) qkv = x @ w_qkv -> x256-scaled fp16 hi/lo planes
    gemm_f16x3<true><<<dim3(D3 / 128, SEQ / 128), 256, gemm_smem>>>(
        xh, xl, wqh, wql, nullptr, qkvh, qkvl, SEQ, D3, DMODEL, 1.f / 256.f);

    // 2) sliding-window attention (sorted 1D grid)
    attn_f16v8<<<512, 256, A_SMEM>>>(qkvh, qkvl, ath, atl);

    // 3) out = attn @ w_out (fp32 out)
    gemm_f16x3<false><<<dim3(DMODEL / 128, SEQ / 128), 256, gemm_smem>>>(
        ath, atl, woh, wol, out, nullptr, nullptr, SEQ, DMODEL, DMODEL,
        1.f / 65536.f);
}